// round 10
// baseline (speedup 1.0000x reference)
#include <cuda_runtime.h>
#include <cstdint>

typedef unsigned long long u64;

#define N_INP   64
#define N_HID   512
#define BATCH   128
#define SEQ     1024
#define DT_C    0.042f
#define CSZ     16      // CTAs per cluster
#define BC      8       // batches per cluster
#define HS      32      // hidden slice per CTA
#define THREADS 256
#define WT_P    516     // Wt row pitch (floats)
#define HYF_P   516     // hy_full row pitch (floats)

struct __align__(16) Smem {
    float Wt[HS * WT_P];          // 66048 B  Wt[h][k] = h2h[k][h0+h] (k-contig)
    float hy_full[BC * HYF_P];    // 16512 B  all-gathered hy, [b][k]
    float wrecv[CSZ * BC * HS];   // 16384 B  [src][b][kin]
    float recD[BC * HS * 2];      //  2048 B  dup pairs (rec, rec)
    float hyStage[BC * HS];       //  1024 B  staging for v4 broadcast
};                                 // 102016 B -> 2 CTAs/SM

__device__ __forceinline__ uint32_t smem_u32(const void* p) {
    uint32_t a;
    asm("{ .reg .u64 t; cvta.to.shared.u64 t, %1; cvt.u32.u64 %0, t; }"
        : "=r"(a) : "l"(p));
    return a;
}
__device__ __forceinline__ uint32_t mapa_u32(uint32_t a, uint32_t r) {
    uint32_t d;
    asm("mapa.shared::cluster.u32 %0, %1, %2;" : "=r"(d) : "r"(a), "r"(r));
    return d;
}
__device__ __forceinline__ void st_cluster_v4(uint32_t a, float4 v) {
    asm volatile("st.shared::cluster.v4.f32 [%0], {%1, %2, %3, %4};"
                 :: "r"(a), "f"(v.x), "f"(v.y), "f"(v.z), "f"(v.w) : "memory");
}
__device__ __forceinline__ uint32_t ctarank() {
    uint32_t r;
    asm("mov.u32 %0, %%cluster_ctarank;" : "=r"(r));
    return r;
}
__device__ __forceinline__ void fma2(u64& d, u64 a, u64 b) {
    asm("fma.rn.f32x2 %0, %1, %2, %0;" : "+l"(d) : "l"(a), "l"(b));
}
__device__ __forceinline__ float2 unpk(u64 v) {
    float2 f;
    asm("mov.b64 {%0, %1}, %2;" : "=f"(f.x), "=f"(f.y) : "l"(v));
    return f;
}
// tanh(x) = 1 - 2/(e^{2x}+1), ex2/rcp approx. ~1e-6 rel err.
__device__ __forceinline__ float ftanh(float x) {
    float e, r;
    asm("ex2.approx.f32 %0, %1;" : "=f"(e) : "f"(x * 2.885390082f));
    asm("rcp.approx.f32 %0, %1;" : "=f"(r) : "f"(e + 1.0f));
    return fmaf(-2.0f, r, 1.0f);
}
#define CLUSTER_SYNC() do { \
    asm volatile("barrier.cluster.arrive.aligned;" ::: "memory"); \
    asm volatile("barrier.cluster.wait.aligned;" ::: "memory"); \
} while (0)

// ===================== prelude: i2h_all = tanh(x @ x2h) -> out ==============
#define PRE_CTAS 512
#define XDP 130
__global__ void __launch_bounds__(512, 1)
i2h_kernel(const float* __restrict__ x, const float* __restrict__ x2h,
           float* __restrict__ out)
{
    extern __shared__ float ps[];
    float* W2 = ps;
    float* xd = ps + 64 * 512;
    const int t = threadIdx.x;

    for (int idx = t; idx < 64 * 512 / 4; idx += 512)
        *reinterpret_cast<float4*>(&W2[idx * 4]) =
            *reinterpret_cast<const float4*>(&x2h[idx * 4]);

    const int hg = t >> 3;
    const int rq = t & 7;
    const long r0 = (long)blockIdx.x * 256;

    for (int tile = 0; tile < 16; ++tile) {
        __syncthreads();
        #pragma unroll
        for (int rr = 0; rr < 2; ++rr) {
            int e = t + rr * 512;
            int row = e >> 6, i = e & 63;
            float v = x[(r0 + tile * 16 + row) * 64 + i];
            *reinterpret_cast<float2*>(&xd[row * XDP + i * 2]) = make_float2(v, v);
        }
        __syncthreads();

        u64 acc[2][4];
        #pragma unroll
        for (int a = 0; a < 2; ++a)
            #pragma unroll
            for (int b = 0; b < 4; ++b) acc[a][b] = 0ull;

        const float* xe_p = &xd[(rq * 2 + 0) * XDP];
        const float* xo_p = &xd[(rq * 2 + 1) * XDP];
        #pragma unroll 8
        for (int i = 0; i < 64; ++i) {
            ulonglong2 wA = *reinterpret_cast<const ulonglong2*>(&W2[i * 512 + hg * 8]);
            ulonglong2 wB = *reinterpret_cast<const ulonglong2*>(&W2[i * 512 + hg * 8 + 4]);
            u64 xe = *reinterpret_cast<const u64*>(&xe_p[i * 2]);
            u64 xo = *reinterpret_cast<const u64*>(&xo_p[i * 2]);
            fma2(acc[0][0], wA.x, xe); fma2(acc[0][1], wA.y, xe);
            fma2(acc[0][2], wB.x, xe); fma2(acc[0][3], wB.y, xe);
            fma2(acc[1][0], wA.x, xo); fma2(acc[1][1], wA.y, xo);
            fma2(acc[1][2], wB.x, xo); fma2(acc[1][3], wB.y, xo);
        }
        #pragma unroll
        for (int rr = 0; rr < 2; ++rr) {
            long row = r0 + tile * 16 + rq * 2 + rr;
            float4 o0, o1; float2 f;
            f = unpk(acc[rr][0]); o0.x = ftanh(f.x); o0.y = ftanh(f.y);
            f = unpk(acc[rr][1]); o0.z = ftanh(f.x); o0.w = ftanh(f.y);
            f = unpk(acc[rr][2]); o1.x = ftanh(f.x); o1.y = ftanh(f.y);
            f = unpk(acc[rr][3]); o1.z = ftanh(f.x); o1.w = ftanh(f.y);
            *reinterpret_cast<float4*>(&out[row * 512 + hg * 8])     = o0;
            *reinterpret_cast<float4*>(&out[row * 512 + hg * 8 + 4]) = o1;
        }
    }
}

// ===================== main recurrence (16-CTA cluster, 2 CTA/SM) ===========
__global__ void __launch_bounds__(THREADS, 2)
piron_kernel(const float* __restrict__ h2h,
             const float* __restrict__ bias,
             const float* __restrict__ gamma,
             const float* __restrict__ eps,
             float* outp,
             int out_size)
{
    extern __shared__ Smem smem[];
    Smem& S = smem[0];
    const int      t       = threadIdx.x;
    const uint32_t rank    = ctarank();
    const int      cluster = blockIdx.x / CSZ;
    const int      h0      = (int)rank * HS;

    // ---- init: Wt[h][k] = h2h[k][h0+h] (transposed, k-contiguous) ----
    for (int idx = t; idx < HS * N_HID; idx += THREADS) {
        int h = idx & 31, k = idx >> 5;
        S.Wt[h * WT_P + k] = h2h[(size_t)k * N_HID + h0 + h];
    }
    for (int idx = t; idx < BC * HYF_P; idx += THREADS) S.hy_full[idx] = 0.f;
    __syncthreads();
    CLUSTER_SYNC();

    // ---- thread roles ----
    const int b  = t >> 5;     // batch (B, D, E)
    const int h  = t & 31;     // h within slice (B, E-update)
    const int kq = t & 31;     // k-quad (D)

    // ---- persistent per-thread state (registers) ----
    const float bs = bias[h0 + h];
    const float gm = gamma[h0 + h];
    const float ep = eps[h0 + h];
    float hy = 0.f, hz = 0.f;

    // D scatter bases: k = kq*4 + off*128 -> peer = (kq>>3)+off*4, kin = (kq&7)*4
    uint32_t sc[4];
    {
        uint32_t loc = smem_u32(&S.wrecv[(int)rank * (BC * HS) + b * HS + (kq & 7) * 4]);
        #pragma unroll
        for (int off = 0; off < 4; ++off)
            sc[off] = mapa_u32(loc, (uint32_t)((kq >> 3) + off * 4));
    }
    // E broadcast bases: unit u = t&63 -> (ub2 = u>>3, q = u&7); peers pg*4..pg*4+3
    const int ub2 = (t & 63) >> 3;
    const int uq  = t & 7;
    uint32_t hbb[4];
    {
        uint32_t loc = smem_u32(&S.hy_full[ub2 * HYF_P + h0 + uq * 4]);
        #pragma unroll
        for (int p = 0; p < 4; ++p)
            hbb[p] = mapa_u32(loc, (uint32_t)((t >> 6) * 4 + p));
    }
    // out pointer for this thread's (b, h)
    float* po = outp + (size_t)(cluster * BC + b) * SEQ * N_HID + h0 + h;

    for (int step = 0; step < SEQ; ++step) {
        // i2h prefetch (consumed in E, ~3 barriers later)
        float i2 = po[(size_t)step * N_HID];

        // ---- B: rec[b][h] = tanh(sum_k hy[b][k] * Wt[h][k] + bias) ----
        {
            const float* wrow  = &S.Wt[h * WT_P];
            const float* hyrow = &S.hy_full[b * HYF_P];
            u64 a0 = 0, a1 = 0, a2 = 0, a3 = 0;
            #pragma unroll 8
            for (int j = 0; j < 128; j += 2) {
                ulonglong2 w0 = *reinterpret_cast<const ulonglong2*>(&wrow[j * 4]);
                ulonglong2 v0 = *reinterpret_cast<const ulonglong2*>(&hyrow[j * 4]);
                ulonglong2 w1 = *reinterpret_cast<const ulonglong2*>(&wrow[j * 4 + 4]);
                ulonglong2 v1 = *reinterpret_cast<const ulonglong2*>(&hyrow[j * 4 + 4]);
                fma2(a0, w0.x, v0.x); fma2(a1, w0.y, v0.y);
                fma2(a2, w1.x, v1.x); fma2(a3, w1.y, v1.y);
            }
            float2 f0 = unpk(a0), f1 = unpk(a1), f2 = unpk(a2), f3 = unpk(a3);
            float rec = ftanh(((f0.x + f0.y) + (f1.x + f1.y)) +
                              ((f2.x + f2.y) + (f3.x + f3.y)) + bs);
            *reinterpret_cast<float2*>(&S.recD[(b * HS + h) * 2]) =
                make_float2(rec, rec);
        }
        __syncthreads();

        // ---- D: w[b][k] partial over h-slice; k = kq*4 + off*128 ----
        {
            const float* rp = &S.recD[b * HS * 2];
            const float* wb = &S.Wt[kq * 4];
            u64 acc[8];
            #pragma unroll
            for (int q = 0; q < 8; ++q) acc[q] = 0ull;
            #pragma unroll 4
            for (int hh = 0; hh < HS; ++hh) {
                u64 rd = *reinterpret_cast<const u64*>(&rp[hh * 2]);
                const float* wr = wb + hh * WT_P;
                ulonglong2 w0 = *reinterpret_cast<const ulonglong2*>(wr);
                ulonglong2 w1 = *reinterpret_cast<const ulonglong2*>(wr + 128);
                ulonglong2 w2 = *reinterpret_cast<const ulonglong2*>(wr + 256);
                ulonglong2 w3 = *reinterpret_cast<const ulonglong2*>(wr + 384);
                fma2(acc[0], w0.x, rd); fma2(acc[1], w0.y, rd);
                fma2(acc[2], w1.x, rd); fma2(acc[3], w1.y, rd);
                fma2(acc[4], w2.x, rd); fma2(acc[5], w2.y, rd);
                fma2(acc[6], w3.x, rd); fma2(acc[7], w3.y, rd);
            }
            #pragma unroll
            for (int off = 0; off < 4; ++off) {
                float2 lo = unpk(acc[off * 2]);
                float2 hi = unpk(acc[off * 2 + 1]);
                float4 o; o.x = lo.x; o.y = lo.y; o.z = hi.x; o.w = hi.y;
                st_cluster_v4(sc[off], o);
            }
        }
        CLUSTER_SYNC();   // all scatters delivered cluster-wide

        // ---- E: reduce 16 partials, update state, emit, stage hy ----
        {
            float w = 0.f;
            #pragma unroll
            for (int src = 0; src < CSZ; ++src)
                w += S.wrecv[src * (BC * HS) + b * HS + h];
            hz += DT_C * (i2 - w - gm * hy - ep * hz);
            hy += DT_C * hz;
            po[(size_t)step * N_HID] = hy;
            S.hyStage[b * HS + h] = hy;
        }
        __syncthreads();

        // ---- broadcast hy (v4) into all 16 CTAs' hy_full ----
        {
            float4 v = *reinterpret_cast<const float4*>(
                &S.hyStage[ub2 * HS + uq * 4]);
            #pragma unroll
            for (int p = 0; p < 4; ++p) st_cluster_v4(hbb[p], v);
        }
        CLUSTER_SYNC();   // hy_full consistent before next step
    }

    // ---- final hy appended after states ----
    if (out_size >= BATCH * SEQ * N_HID + BATCH * N_HID) {
        outp[(size_t)BATCH * SEQ * N_HID +
             (size_t)(cluster * BC + b) * N_HID + h0 + h] = hy;
    }
}

extern "C" void kernel_launch(void* const* d_in, const int* in_sizes, int n_in,
                              void* d_out, int out_size) {
    (void)in_sizes; (void)n_in;
    const float* x     = (const float*)d_in[0];
    const float* x2h   = (const float*)d_in[1];
    const float* h2h   = (const float*)d_in[2];
    const float* bias  = (const float*)d_in[3];
    const float* gamma = (const float*)d_in[4];
    const float* eps   = (const float*)d_in[5];
    float* out = (float*)d_out;

    const int pre_smem = (64 * 512 + 16 * XDP) * 4;
    cudaFuncSetAttribute(i2h_kernel,
                         cudaFuncAttributeMaxDynamicSharedMemorySize, pre_smem);
    cudaFuncSetAttribute(piron_kernel,
                         cudaFuncAttributeMaxDynamicSharedMemorySize,
                         (int)sizeof(Smem));
    cudaFuncSetAttribute(piron_kernel,
                         cudaFuncAttributeNonPortableClusterSizeAllowed, 1);

    i2h_kernel<<<PRE_CTAS, 512, pre_smem>>>(x, x2h, out);

    // 16 clusters x 16 CTAs = 256 CTAs, 2 CTAs/SM co-resident
    cudaLaunchConfig_t cfg = {};
    cfg.gridDim  = dim3((BATCH / BC) * CSZ, 1, 1);
    cfg.blockDim = dim3(THREADS, 1, 1);
    cfg.dynamicSmemBytes = sizeof(Smem);
    cudaLaunchAttribute attrs[1];
    attrs[0].id = cudaLaunchAttributeClusterDimension;
    attrs[0].val.clusterDim = {CSZ, 1, 1};
    cfg.attrs = attrs;
    cfg.numAttrs = 1;
    cudaLaunchKernelEx(&cfg, piron_kernel, h2h, bias, gamma, eps, out, out_size);
}

// round 11
// speedup vs baseline: 1.1499x; 1.1499x over previous
#include <cuda_runtime.h>
#include <cstdint>

typedef unsigned long long u64;

#define N_INP   64
#define N_HID   512
#define BATCH   128
#define SEQ     1024
#define DT_C    0.042f
#define CSZ     8
#define BC      8
#define HS      64
#define THREADS 256
#define HYF_P   516     // hy_full row pitch (floats)

struct __align__(16) Smem {
    float4 W[512 * 16];           // 131072 B  h2h[:,slice], slot = gq ^ (k&15)
    float  hy_full[BC * HYF_P];   //  16512 B  all-gathered hy, [b][k]
    float  wrecv[CSZ * BC * HS];  //  16384 B  [src][b][kin]
    float  recF[BC * HS];         //   2048 B  rec[b][h]
};                                 // ~166 KB

__device__ __forceinline__ uint32_t smem_u32(const void* p) {
    uint32_t a;
    asm("{ .reg .u64 t; cvta.to.shared.u64 t, %1; cvt.u32.u64 %0, t; }"
        : "=r"(a) : "l"(p));
    return a;
}
__device__ __forceinline__ uint32_t mapa_u32(uint32_t a, uint32_t r) {
    uint32_t d;
    asm("mapa.shared::cluster.u32 %0, %1, %2;" : "=r"(d) : "r"(a), "r"(r));
    return d;
}
__device__ __forceinline__ void st_cluster_f32(uint32_t a, float v) {
    asm volatile("st.shared::cluster.f32 [%0], %1;" :: "r"(a), "f"(v) : "memory");
}
__device__ __forceinline__ void st_cluster_u64(uint32_t a, u64 v) {
    asm volatile("st.shared::cluster.u64 [%0], %1;" :: "r"(a), "l"(v) : "memory");
}
__device__ __forceinline__ uint32_t ctarank() {
    uint32_t r;
    asm("mov.u32 %0, %%cluster_ctarank;" : "=r"(r));
    return r;
}
__device__ __forceinline__ void fma2(u64& d, u64 a, u64 b) {
    asm("fma.rn.f32x2 %0, %1, %2, %0;" : "+l"(d) : "l"(a), "l"(b));
}
__device__ __forceinline__ float2 unpk(u64 v) {
    float2 f;
    asm("mov.b64 {%0, %1}, %2;" : "=f"(f.x), "=f"(f.y) : "l"(v));
    return f;
}
__device__ __forceinline__ u64 dup_f32(float v) {
    u64 d;
    asm("mov.b64 %0, {%1, %1};" : "=l"(d) : "f"(v));
    return d;
}
__device__ __forceinline__ u64 pack2(float a, float b) {
    u64 d;
    asm("mov.b64 %0, {%1, %2};" : "=l"(d) : "f"(a), "f"(b));
    return d;
}
// tanh(x) = 1 - 2/(e^{2x}+1), ex2/rcp approx. ~1e-6 rel err.
__device__ __forceinline__ float ftanh(float x) {
    float e, r;
    asm("ex2.approx.f32 %0, %1;" : "=f"(e) : "f"(x * 2.885390082f));
    asm("rcp.approx.f32 %0, %1;" : "=f"(r) : "f"(e + 1.0f));
    return fmaf(-2.0f, r, 1.0f);
}
#define CLUSTER_SYNC() do { \
    asm volatile("barrier.cluster.arrive.aligned;" ::: "memory"); \
    asm volatile("barrier.cluster.wait.aligned;" ::: "memory"); \
} while (0)

// ===================== prelude: i2h_all = tanh(x @ x2h) -> out ==============
#define PRE_CTAS 512
#define XDP 130
__global__ void __launch_bounds__(512, 1)
i2h_kernel(const float* __restrict__ x, const float* __restrict__ x2h,
           float* __restrict__ out)
{
    extern __shared__ float ps[];
    float* W2 = ps;
    float* xd = ps + 64 * 512;
    const int t = threadIdx.x;

    for (int idx = t; idx < 64 * 512 / 4; idx += 512)
        *reinterpret_cast<float4*>(&W2[idx * 4]) =
            *reinterpret_cast<const float4*>(&x2h[idx * 4]);

    const int hg = t >> 3;
    const int rq = t & 7;
    const long r0 = (long)blockIdx.x * 256;

    for (int tile = 0; tile < 16; ++tile) {
        __syncthreads();
        #pragma unroll
        for (int rr = 0; rr < 2; ++rr) {
            int e = t + rr * 512;
            int row = e >> 6, i = e & 63;
            float v = x[(r0 + tile * 16 + row) * 64 + i];
            *reinterpret_cast<float2*>(&xd[row * XDP + i * 2]) = make_float2(v, v);
        }
        __syncthreads();

        u64 acc[2][4];
        #pragma unroll
        for (int a = 0; a < 2; ++a)
            #pragma unroll
            for (int b = 0; b < 4; ++b) acc[a][b] = 0ull;

        const float* xe_p = &xd[(rq * 2 + 0) * XDP];
        const float* xo_p = &xd[(rq * 2 + 1) * XDP];
        #pragma unroll 8
        for (int i = 0; i < 64; ++i) {
            ulonglong2 wA = *reinterpret_cast<const ulonglong2*>(&W2[i * 512 + hg * 8]);
            ulonglong2 wB = *reinterpret_cast<const ulonglong2*>(&W2[i * 512 + hg * 8 + 4]);
            u64 xe = *reinterpret_cast<const u64*>(&xe_p[i * 2]);
            u64 xo = *reinterpret_cast<const u64*>(&xo_p[i * 2]);
            fma2(acc[0][0], wA.x, xe); fma2(acc[0][1], wA.y, xe);
            fma2(acc[0][2], wB.x, xe); fma2(acc[0][3], wB.y, xe);
            fma2(acc[1][0], wA.x, xo); fma2(acc[1][1], wA.y, xo);
            fma2(acc[1][2], wB.x, xo); fma2(acc[1][3], wB.y, xo);
        }
        #pragma unroll
        for (int rr = 0; rr < 2; ++rr) {
            long row = r0 + tile * 16 + rq * 2 + rr;
            float4 o0, o1; float2 f;
            f = unpk(acc[rr][0]); o0.x = ftanh(f.x); o0.y = ftanh(f.y);
            f = unpk(acc[rr][1]); o0.z = ftanh(f.x); o0.w = ftanh(f.y);
            f = unpk(acc[rr][2]); o1.x = ftanh(f.x); o1.y = ftanh(f.y);
            f = unpk(acc[rr][3]); o1.z = ftanh(f.x); o1.w = ftanh(f.y);
            *reinterpret_cast<float4*>(&out[row * 512 + hg * 8])     = o0;
            *reinterpret_cast<float4*>(&out[row * 512 + hg * 8 + 4]) = o1;
        }
    }
}

// ===================== main recurrence =====================================
__global__ void __launch_bounds__(THREADS, 1) __cluster_dims__(CSZ, 1, 1)
piron_kernel(const float* __restrict__ h2h,
             const float* __restrict__ bias,
             const float* __restrict__ gamma,
             const float* __restrict__ eps,
             float* outp,
             int out_size)
{
    extern __shared__ Smem smem[];
    Smem& S = smem[0];
    const int      t       = threadIdx.x;
    const uint32_t rank    = ctarank();
    const int      cluster = blockIdx.x / CSZ;
    const int      h0      = (int)rank * HS;

    // ---- init: W swizzled (quad gq of row k at slot gq^(k&15)) ----
    for (int idx = t; idx < 512 * 16; idx += THREADS) {
        int k = idx >> 4, gq = idx & 15;
        float4 v = *reinterpret_cast<const float4*>(h2h + (size_t)k * N_HID + h0 + gq * 4);
        S.W[(k << 4) | (gq ^ (k & 15))] = v;
    }
    for (int idx = t; idx < BC * HYF_P; idx += THREADS) S.hy_full[idx] = 0.f;
    __syncthreads();
    CLUSTER_SYNC();

    // ---- thread roles ----
    // B (pass1): warp = batch b1; lane = g8 (h-octet) | ksl<<3 (k mod 4)
    const int lane = t & 31;
    const int g8   = lane & 7;
    const int ksl  = lane >> 3;
    const int b1   = t >> 5;
    // D (pass2): kq = t&127 owns rows kq+128r; bh = t>>7 owns 4 batches
    const int kq = t & 127;
    const int bh = t >> 7;
    // E (update): eb = t>>5 batch, h2 = even h pair
    const int eb = t >> 5;
    const int h2 = (t & 31) * 2;

    // ---- persistent per-thread state (registers) ----
    // pass1 bias quads (h = g8*4.. and (g8+8)*4..)
    const float4 bias_lo = *reinterpret_cast<const float4*>(bias + h0 + g8 * 4);
    const float4 bias_hi = *reinterpret_cast<const float4*>(bias + h0 + g8 * 4 + 32);
    // E constants + state
    const float2 gm = *reinterpret_cast<const float2*>(gamma + h0 + h2);
    const float2 ep = *reinterpret_cast<const float2*>(eps   + h0 + h2);
    float hy0 = 0.f, hy1 = 0.f, hz0 = 0.f, hz1 = 0.f;

    // D scatter bases: k = kq + 128r -> peer (kq>>6)+2r, kin = kq&63
    uint32_t sc[4];
    {
        uint32_t loc = smem_u32(&S.wrecv[(int)rank * 512 + (kq & 63)]);
        #pragma unroll
        for (int r = 0; r < 4; ++r)
            sc[r] = mapa_u32(loc, (uint32_t)((kq >> 6) + 2 * r));
    }
    // E broadcast addresses into every CTA's hy_full
    uint32_t hb[CSZ];
    {
        uint32_t loc = smem_u32(&S.hy_full[eb * HYF_P + h0 + h2]);
        #pragma unroll
        for (uint32_t p = 0; p < CSZ; ++p) hb[p] = mapa_u32(loc, p);
    }
    // out pointer for this thread's (eb, h-pair)
    float* po = outp + (size_t)(cluster * BC + eb) * SEQ * N_HID + h0 + h2;

    for (int step = 0; step < SEQ; ++step) {
        // i2h prefetch (consumed in E)
        float2 i2 = *reinterpret_cast<const float2*>(po + (size_t)step * N_HID);

        // ---- B: pass1.  k = 4j + ksl; thread owns h-quads g8, g8+8 ----
        {
            const float* hyp = &S.hy_full[b1 * HYF_P + ksl];
            u64 a0 = 0, a1 = 0, a2 = 0, a3 = 0;
            #pragma unroll 8
            for (int j = 0; j < 128; ++j) {
                int k = 4 * j + ksl;
                int c = k & 15;
                const float4* row = S.W + (k << 4);
                ulonglong2 wlo = *reinterpret_cast<const ulonglong2*>(row + (g8 ^ c));
                ulonglong2 whi = *reinterpret_cast<const ulonglong2*>(row + ((g8 + 8) ^ c));
                u64 hv = dup_f32(hyp[4 * j]);
                fma2(a0, wlo.x, hv); fma2(a1, wlo.y, hv);
                fma2(a2, whi.x, hv); fma2(a3, whi.y, hv);
            }
            float2 f0 = unpk(a0), f1 = unpk(a1), f2 = unpk(a2), f3 = unpk(a3);
            // reduce over ksl (lane bits 3,4)
            #define RED(v) \
                v += __shfl_xor_sync(0xffffffffu, v, 8);  \
                v += __shfl_xor_sync(0xffffffffu, v, 16);
            RED(f0.x) RED(f0.y) RED(f1.x) RED(f1.y)
            RED(f2.x) RED(f2.y) RED(f3.x) RED(f3.y)
            #undef RED
            if (lane < 16) {
                bool lo = lane < 8;
                float s0 = lo ? f0.x : f2.x;
                float s1 = lo ? f0.y : f2.y;
                float s2 = lo ? f1.x : f3.x;
                float s3 = lo ? f1.y : f3.y;
                float4 bb = lo ? bias_lo : bias_hi;
                float4 o;
                o.x = ftanh(s0 + bb.x); o.y = ftanh(s1 + bb.y);
                o.z = ftanh(s2 + bb.z); o.w = ftanh(s3 + bb.w);
                int off = g8 * 4 + (lo ? 0 : 32);
                *reinterpret_cast<float4*>(&S.recF[b1 * 64 + off]) = o;
            }
        }
        __syncthreads();

        // ---- D: pass2. rows k = kq + 128r, batches bh*4..+3 ----
        {
            const int swz = kq & 15;
            u64 acc[4][4];   // [r][bb]
            #pragma unroll
            for (int r = 0; r < 4; ++r)
                #pragma unroll
                for (int bb = 0; bb < 4; ++bb) acc[r][bb] = 0ull;
            #pragma unroll 4
            for (int gg = 0; gg < 16; ++gg) {
                int slot = gg ^ swz;
                ulonglong2 w0 = *reinterpret_cast<const ulonglong2*>(S.W + ((kq +   0) << 4) + slot);
                ulonglong2 w1 = *reinterpret_cast<const ulonglong2*>(S.W + ((kq + 128) << 4) + slot);
                ulonglong2 w2 = *reinterpret_cast<const ulonglong2*>(S.W + ((kq + 256) << 4) + slot);
                ulonglong2 w3 = *reinterpret_cast<const ulonglong2*>(S.W + ((kq + 384) << 4) + slot);
                #pragma unroll
                for (int bb = 0; bb < 4; ++bb) {
                    ulonglong2 r2 = *reinterpret_cast<const ulonglong2*>(
                        &S.recF[(bh * 4 + bb) * 64 + gg * 4]);
                    fma2(acc[0][bb], w0.x, r2.x); fma2(acc[0][bb], w0.y, r2.y);
                    fma2(acc[1][bb], w1.x, r2.x); fma2(acc[1][bb], w1.y, r2.y);
                    fma2(acc[2][bb], w2.x, r2.x); fma2(acc[2][bb], w2.y, r2.y);
                    fma2(acc[3][bb], w3.x, r2.x); fma2(acc[3][bb], w3.y, r2.y);
                }
            }
            #pragma unroll
            for (int r = 0; r < 4; ++r)
                #pragma unroll
                for (int bb = 0; bb < 4; ++bb) {
                    float2 f = unpk(acc[r][bb]);
                    st_cluster_f32(sc[r] + (uint32_t)((bh * 4 + bb) * 256),
                                   f.x + f.y);
                }
        }
        CLUSTER_SYNC();   // scatter complete everywhere

        // ---- E: reduce 8 partials, update state, emit, all-gather hy ----
        {
            float2 w = make_float2(0.f, 0.f);
            #pragma unroll
            for (int src = 0; src < 8; ++src) {
                float2 u = *reinterpret_cast<const float2*>(
                    &S.wrecv[src * 512 + eb * 64 + h2]);
                w.x += u.x; w.y += u.y;
            }
            hz0 += DT_C * (i2.x - w.x - gm.x * hy0 - ep.x * hz0);
            hz1 += DT_C * (i2.y - w.y - gm.y * hy1 - ep.y * hz1);
            hy0 += DT_C * hz0;
            hy1 += DT_C * hz1;
            *reinterpret_cast<float2*>(po + (size_t)step * N_HID) =
                make_float2(hy0, hy1);
            u64 d = pack2(hy0, hy1);
            #pragma unroll
            for (uint32_t p = 0; p < CSZ; ++p) st_cluster_u64(hb[p], d);
        }
        CLUSTER_SYNC();   // hy_full consistent before next step
    }

    // ---- final hy appended after states ----
    if (out_size >= BATCH * SEQ * N_HID + BATCH * N_HID) {
        *reinterpret_cast<float2*>(
            outp + (size_t)BATCH * SEQ * N_HID +
            (size_t)(cluster * BC + eb) * N_HID + h0 + h2) = make_float2(hy0, hy1);
    }
}

extern "C" void kernel_launch(void* const* d_in, const int* in_sizes, int n_in,
                              void* d_out, int out_size) {
    (void)in_sizes; (void)n_in;
    const float* x     = (const float*)d_in[0];
    const float* x2h   = (const float*)d_in[1];
    const float* h2h   = (const float*)d_in[2];
    const float* bias  = (const float*)d_in[3];
    const float* gamma = (const float*)d_in[4];
    const float* eps   = (const float*)d_in[5];
    float* out = (float*)d_out;

    const int pre_smem = (64 * 512 + 16 * XDP) * 4;
    cudaFuncSetAttribute(i2h_kernel,
                         cudaFuncAttributeMaxDynamicSharedMemorySize, pre_smem);
    cudaFuncSetAttribute(piron_kernel,
                         cudaFuncAttributeMaxDynamicSharedMemorySize, (int)sizeof(Smem));

    i2h_kernel<<<PRE_CTAS, 512, pre_smem>>>(x, x2h, out);
    piron_kernel<<<(BATCH / BC) * CSZ, THREADS, sizeof(Smem)>>>(
        h2h, bias, gamma, eps, out, out_size);
}

// round 12
// speedup vs baseline: 1.7884x; 1.5553x over previous
#include <cuda_runtime.h>
#include <cstdint>

typedef unsigned long long u64;

#define N_INP   64
#define N_HID   512
#define BATCH   128
#define SEQ     1024
#define DT_C    0.042f
#define CSZ     16      // CTAs per cluster
#define BC      8       // batches per cluster
#define HS      32      // hidden slice per CTA
#define THREADS 256
#define HYF_P   516     // hy_full row pitch (floats)

struct __align__(16) Smem {
    float4 W[512 * 8];            // 65536 B  h2h[:,slice], slot = gq ^ (k&7)
    float  hy_full[BC * HYF_P];   // 16512 B  all-gathered hy, [b][k]
    float  wrecv[CSZ * BC * HS];  // 16384 B  [src][b][kin]
    float4 scratch[8 * 8 * 9];    //  9216 B  pass1 partials [ks][b][quad], pitch 9
    float  recF[BC * HS];         //  1024 B  rec[b][h]
    float  hyStage[BC * HS];      //  1024 B  staging for v4 broadcast
};                                 // 109696 B -> 2 CTAs/SM

__device__ __forceinline__ uint32_t smem_u32(const void* p) {
    uint32_t a;
    asm("{ .reg .u64 t; cvta.to.shared.u64 t, %1; cvt.u32.u64 %0, t; }"
        : "=r"(a) : "l"(p));
    return a;
}
__device__ __forceinline__ uint32_t mapa_u32(uint32_t a, uint32_t r) {
    uint32_t d;
    asm("mapa.shared::cluster.u32 %0, %1, %2;" : "=r"(d) : "r"(a), "r"(r));
    return d;
}
__device__ __forceinline__ void st_cluster_f32(uint32_t a, float v) {
    asm volatile("st.shared::cluster.f32 [%0], %1;" :: "r"(a), "f"(v) : "memory");
}
__device__ __forceinline__ void st_cluster_v4(uint32_t a, float4 v) {
    asm volatile("st.shared::cluster.v4.f32 [%0], {%1, %2, %3, %4};"
                 :: "r"(a), "f"(v.x), "f"(v.y), "f"(v.z), "f"(v.w) : "memory");
}
__device__ __forceinline__ uint32_t ctarank() {
    uint32_t r;
    asm("mov.u32 %0, %%cluster_ctarank;" : "=r"(r));
    return r;
}
__device__ __forceinline__ void fma2(u64& d, u64 a, u64 b) {
    asm("fma.rn.f32x2 %0, %1, %2, %0;" : "+l"(d) : "l"(a), "l"(b));
}
__device__ __forceinline__ float2 unpk(u64 v) {
    float2 f;
    asm("mov.b64 {%0, %1}, %2;" : "=f"(f.x), "=f"(f.y) : "l"(v));
    return f;
}
__device__ __forceinline__ u64 dup_f32(float v) {
    u64 d;
    asm("mov.b64 %0, {%1, %1};" : "=l"(d) : "f"(v));
    return d;
}
// tanh(x) = 1 - 2/(e^{2x}+1), ex2/rcp approx. ~1e-6 rel err.
__device__ __forceinline__ float ftanh(float x) {
    float e, r;
    asm("ex2.approx.f32 %0, %1;" : "=f"(e) : "f"(x * 2.885390082f));
    asm("rcp.approx.f32 %0, %1;" : "=f"(r) : "f"(e + 1.0f));
    return fmaf(-2.0f, r, 1.0f);
}
#define CLUSTER_SYNC() do { \
    asm volatile("barrier.cluster.arrive.aligned;" ::: "memory"); \
    asm volatile("barrier.cluster.wait.aligned;" ::: "memory"); \
} while (0)

// ===================== prelude: i2h_all = tanh(x @ x2h) -> out ==============
#define PRE_CTAS 512
#define XDP 130
__global__ void __launch_bounds__(512, 1)
i2h_kernel(const float* __restrict__ x, const float* __restrict__ x2h,
           float* __restrict__ out)
{
    extern __shared__ float ps[];
    float* W2 = ps;
    float* xd = ps + 64 * 512;
    const int t = threadIdx.x;

    for (int idx = t; idx < 64 * 512 / 4; idx += 512)
        *reinterpret_cast<float4*>(&W2[idx * 4]) =
            *reinterpret_cast<const float4*>(&x2h[idx * 4]);

    const int hg = t >> 3;
    const int rq = t & 7;
    const long r0 = (long)blockIdx.x * 256;

    for (int tile = 0; tile < 16; ++tile) {
        __syncthreads();
        #pragma unroll
        for (int rr = 0; rr < 2; ++rr) {
            int e = t + rr * 512;
            int row = e >> 6, i = e & 63;
            float v = x[(r0 + tile * 16 + row) * 64 + i];
            *reinterpret_cast<float2*>(&xd[row * XDP + i * 2]) = make_float2(v, v);
        }
        __syncthreads();

        u64 acc[2][4];
        #pragma unroll
        for (int a = 0; a < 2; ++a)
            #pragma unroll
            for (int b = 0; b < 4; ++b) acc[a][b] = 0ull;

        const float* xe_p = &xd[(rq * 2 + 0) * XDP];
        const float* xo_p = &xd[(rq * 2 + 1) * XDP];
        #pragma unroll 8
        for (int i = 0; i < 64; ++i) {
            ulonglong2 wA = *reinterpret_cast<const ulonglong2*>(&W2[i * 512 + hg * 8]);
            ulonglong2 wB = *reinterpret_cast<const ulonglong2*>(&W2[i * 512 + hg * 8 + 4]);
            u64 xe = *reinterpret_cast<const u64*>(&xe_p[i * 2]);
            u64 xo = *reinterpret_cast<const u64*>(&xo_p[i * 2]);
            fma2(acc[0][0], wA.x, xe); fma2(acc[0][1], wA.y, xe);
            fma2(acc[0][2], wB.x, xe); fma2(acc[0][3], wB.y, xe);
            fma2(acc[1][0], wA.x, xo); fma2(acc[1][1], wA.y, xo);
            fma2(acc[1][2], wB.x, xo); fma2(acc[1][3], wB.y, xo);
        }
        #pragma unroll
        for (int rr = 0; rr < 2; ++rr) {
            long row = r0 + tile * 16 + rq * 2 + rr;
            float4 o0, o1; float2 f;
            f = unpk(acc[rr][0]); o0.x = ftanh(f.x); o0.y = ftanh(f.y);
            f = unpk(acc[rr][1]); o0.z = ftanh(f.x); o0.w = ftanh(f.y);
            f = unpk(acc[rr][2]); o1.x = ftanh(f.x); o1.y = ftanh(f.y);
            f = unpk(acc[rr][3]); o1.z = ftanh(f.x); o1.w = ftanh(f.y);
            *reinterpret_cast<float4*>(&out[row * 512 + hg * 8])     = o0;
            *reinterpret_cast<float4*>(&out[row * 512 + hg * 8 + 4]) = o1;
        }
    }
}

// ===================== main recurrence (16-CTA cluster, 2 CTA/SM) ===========
__global__ void __launch_bounds__(THREADS, 2)
piron_kernel(const float* __restrict__ h2h,
             const float* __restrict__ bias,
             const float* __restrict__ gamma,
             const float* __restrict__ eps,
             float* outp,
             int out_size)
{
    extern __shared__ Smem smem[];
    Smem& S = smem[0];
    const int      t       = threadIdx.x;
    const uint32_t rank    = ctarank();
    const int      cluster = blockIdx.x / CSZ;
    const int      h0      = (int)rank * HS;

    // ---- init: W swizzled (quad gq of row k at slot gq^(k&7)) ----
    for (int idx = t; idx < 512 * 8; idx += THREADS) {
        int k = idx >> 3, gq = idx & 7;
        float4 v = *reinterpret_cast<const float4*>(h2h + (size_t)k * N_HID + h0 + gq * 4);
        S.W[(k << 3) | (gq ^ (k & 7))] = v;
    }
    for (int idx = t; idx < BC * HYF_P; idx += THREADS) S.hy_full[idx] = 0.f;
    __syncthreads();
    CLUSTER_SYNC();

    // ---- thread roles ----
    // B (pass1): gq quad, bq batch-pair, ks = warp = k-split of 64
    const int gq = t & 7;
    const int bq = (t >> 3) & 3;
    const int ks = t >> 5;
    // C/E: b = t>>5 batch, h = t&31
    const int b = t >> 5;
    const int h = t & 31;

    // ---- persistent per-thread state (registers) ----
    const float bs = bias[h0 + h];
    const float gm = gamma[h0 + h];
    const float ep = eps[h0 + h];
    float hy = 0.f, hz = 0.f;

    // D scatter bases: rows k0=t (peer t>>5), k1=t+256 (peer (t>>5)+8); kin=t&31
    const uint32_t sc_loc = smem_u32(&S.wrecv[(int)rank * (BC * HS) + (t & 31)]);
    const uint32_t sc0 = mapa_u32(sc_loc, (uint32_t)(t >> 5));
    const uint32_t sc1 = mapa_u32(sc_loc, (uint32_t)(t >> 5) + 8);
    // E broadcast: unit = t&63 covers float4 of hyStage; peers (t>>6)*4 + p
    const int unit = t & 63;
    uint32_t hbb[4];
    {
        int bu = unit >> 3, q = unit & 7;
        uint32_t loc = smem_u32(&S.hy_full[bu * HYF_P + h0 + q * 4]);
        #pragma unroll
        for (int p = 0; p < 4; ++p)
            hbb[p] = mapa_u32(loc, (uint32_t)((t >> 6) * 4 + p));
    }
    // out pointer for this thread's (b, h)
    float* po = outp + (size_t)(cluster * BC + b) * SEQ * N_HID + h0 + h;

    const float* scF = reinterpret_cast<const float*>(S.scratch);

    for (int step = 0; step < SEQ; ++step) {
        // i2h prefetch (consumed in E)
        float i2 = po[(size_t)step * N_HID];

        // ---- B: pass1 partials; warp ks owns k = ks*64 + j ----
        {
            const float* hyb0 = &S.hy_full[(2 * bq + 0) * HYF_P + ks * 64];
            const float* hyb1 = &S.hy_full[(2 * bq + 1) * HYF_P + ks * 64];
            const float4* Wp = S.W + (ks << 9);   // ks*64 rows * 8 quads
            u64 a00 = 0, a01 = 0, a10 = 0, a11 = 0;
            #pragma unroll 8
            for (int j = 0; j < 64; ++j) {
                // (ks*64 + j) & 7 == j & 7
                ulonglong2 w2 = *reinterpret_cast<const ulonglong2*>(
                    Wp + (j << 3) + (gq ^ (j & 7)));
                u64 h0v = dup_f32(hyb0[j]);
                u64 h1v = dup_f32(hyb1[j]);
                fma2(a00, w2.x, h0v); fma2(a01, w2.y, h0v);
                fma2(a10, w2.x, h1v); fma2(a11, w2.y, h1v);
            }
            ulonglong2 s;
            int r0 = (ks * 8 + 2 * bq) * 9 + gq;
            s.x = a00; s.y = a01;
            *reinterpret_cast<ulonglong2*>(&S.scratch[r0]) = s;
            s.x = a10; s.y = a11;
            *reinterpret_cast<ulonglong2*>(&S.scratch[r0 + 9]) = s;
        }
        __syncthreads();

        // ---- C: reduce 8 k-splits + bias + tanh -> recF ----
        {
            float v = bs;
            #pragma unroll
            for (int s = 0; s < 8; ++s)
                v += scF[((s * 8 + b) * 9 + (h >> 2)) * 4 + (h & 3)];
            S.recF[b * HS + h] = ftanh(v);
        }
        __syncthreads();

        // ---- D: pass2, thread owns rows k0=t, k1=t+256 for all 8 b ----
        {
            const float4* W0 = S.W + (t << 3);
            const float4* W1 = S.W + ((t + 256) << 3);
            const int swz = t & 7;
            u64 acc0[8], acc1[8];
            #pragma unroll
            for (int bb = 0; bb < 8; ++bb) { acc0[bb] = 0ull; acc1[bb] = 0ull; }
            #pragma unroll
            for (int gg = 0; gg < 8; ++gg) {
                int slot = gg ^ swz;
                ulonglong2 w0 = *reinterpret_cast<const ulonglong2*>(W0 + slot);
                ulonglong2 w1 = *reinterpret_cast<const ulonglong2*>(W1 + slot);
                #pragma unroll
                for (int bb = 0; bb < 8; ++bb) {
                    ulonglong2 r2 = *reinterpret_cast<const ulonglong2*>(
                        &S.recF[bb * HS + gg * 4]);
                    fma2(acc0[bb], w0.x, r2.x); fma2(acc0[bb], w0.y, r2.y);
                    fma2(acc1[bb], w1.x, r2.x); fma2(acc1[bb], w1.y, r2.y);
                }
            }
            #pragma unroll
            for (int bb = 0; bb < 8; ++bb) {
                float2 f0 = unpk(acc0[bb]);
                float2 f1 = unpk(acc1[bb]);
                st_cluster_f32(sc0 + (uint32_t)(bb * HS * 4), f0.x + f0.y);
                st_cluster_f32(sc1 + (uint32_t)(bb * HS * 4), f1.x + f1.y);
            }
        }
        CLUSTER_SYNC();   // scatter complete everywhere

        // ---- E: reduce 16 partials, update state, emit, stage hy ----
        {
            float w = 0.f;
            #pragma unroll
            for (int src = 0; src < CSZ; ++src)
                w += S.wrecv[src * (BC * HS) + b * HS + h];
            hz += DT_C * (i2 - w - gm * hy - ep * hz);
            hy += DT_C * hz;
            po[(size_t)step * N_HID] = hy;
            S.hyStage[b * HS + h] = hy;
        }
        __syncthreads();

        // ---- broadcast hy (v4) into all 16 CTAs' hy_full ----
        {
            float4 v = *reinterpret_cast<const float4*>(&S.hyStage[unit * 4]);
            #pragma unroll
            for (int p = 0; p < 4; ++p) st_cluster_v4(hbb[p], v);
        }
        CLUSTER_SYNC();   // hy_full consistent before next step
    }

    // ---- final hy appended after states ----
    if (out_size >= BATCH * SEQ * N_HID + BATCH * N_HID) {
        outp[(size_t)BATCH * SEQ * N_HID +
             (size_t)(cluster * BC + b) * N_HID + h0 + h] = hy;
    }
}

extern "C" void kernel_launch(void* const* d_in, const int* in_sizes, int n_in,
                              void* d_out, int out_size) {
    (void)in_sizes; (void)n_in;
    const float* x     = (const float*)d_in[0];
    const float* x2h   = (const float*)d_in[1];
    const float* h2h   = (const float*)d_in[2];
    const float* bias  = (const float*)d_in[3];
    const float* gamma = (const float*)d_in[4];
    const float* eps   = (const float*)d_in[5];
    float* out = (float*)d_out;

    const int pre_smem = (64 * 512 + 16 * XDP) * 4;
    cudaFuncSetAttribute(i2h_kernel,
                         cudaFuncAttributeMaxDynamicSharedMemorySize, pre_smem);
    cudaFuncSetAttribute(piron_kernel,
                         cudaFuncAttributeMaxDynamicSharedMemorySize,
                         (int)sizeof(Smem));
    cudaFuncSetAttribute(piron_kernel,
                         cudaFuncAttributeNonPortableClusterSizeAllowed, 1);

    i2h_kernel<<<PRE_CTAS, 512, pre_smem>>>(x, x2h, out);

    // 16 clusters x 16 CTAs = 256 CTAs -> 2 CTAs/SM co-resident
    cudaLaunchConfig_t cfg = {};
    cfg.gridDim  = dim3((BATCH / BC) * CSZ, 1, 1);
    cfg.blockDim = dim3(THREADS, 1, 1);
    cfg.dynamicSmemBytes = sizeof(Smem);
    cudaLaunchAttribute attrs[1];
    attrs[0].id = cudaLaunchAttributeClusterDimension;
    attrs[0].val.clusterDim = {CSZ, 1, 1};
    cfg.attrs = attrs;
    cfg.numAttrs = 1;
    cudaLaunchKernelEx(&cfg, piron_kernel, h2h, bias, gamma, eps, out, out_size);
}